// round 9
// baseline (speedup 1.0000x reference)
#include <cuda_runtime.h>
#include <cstdint>

// LSTM B=4096 T=256 I=8 H=32 O=1.
// NB=8: warp = 8 batches; lane j = hidden unit j. f32x2 lanes = GATE pairs
// {z_i,z_f},{z_g,z_o}. Balanced register budget: wif (gates i,f) in 64 regs;
// wgo (gates g,o) in smem packed 2-k per ulonglong2 (one per-lane LDS.128 per
// 2 k-iters). h and x pre-duplicated ({v,v} u64) in shared -> broadcast LDS.
// Cross-step pipelines: x-projection of step s+1 overlaps step s's activation
// chain (branch-free); x LDG for chunk tc+1 prefetched into registers during
// chunk tc compute. Single h buffer (syncwarp-bracketed).
// Sigmoid 0.5 folded into weights/biases (i,f,o).
// CTA = 128 thr (4 warps, 32 batches), grid = 128 -> 1 CTA per SM.

#define B_TOT 4096
#define T_TOT 256
#define I_SZ 8
#define CHUNK 8
#define NCHUNK (T_TOT / CHUNK)

// shared strides (in u64 units)
#define HK_STRIDE 10            // 8 dups + 2 pad -> 4-wf STS.128, 16B-aligned
#define XI_STRIDE 8
#define XT_STRIDE 66            // 8*8 + 2 pad

typedef unsigned long long u64;

__device__ __forceinline__ u64 pack2(float a, float b) {
    u64 r; asm("mov.b64 %0,{%1,%2};" : "=l"(r) : "f"(a), "f"(b)); return r;
}
__device__ __forceinline__ void unpack2(u64 v, float& a, float& b) {
    asm("mov.b64 {%0,%1},%2;" : "=f"(a), "=f"(b) : "l"(v));
}
__device__ __forceinline__ u64 fma2(u64 a, u64 b, u64 c) {
    u64 d; asm("fma.rn.f32x2 %0,%1,%2,%3;" : "=l"(d) : "l"(a), "l"(b), "l"(c)); return d;
}
__device__ __forceinline__ float tanhap(float x) {
    float y; asm("tanh.approx.f32 %0,%1;" : "=f"(y) : "f"(x)); return y;
}
// i,f,o accumulators pre-scaled by 0.5: sigmoid(z)=0.5*tanh(z/2)+0.5
__device__ __forceinline__ float sig_h(float zhalf) {
    return fmaf(0.5f, tanhap(zhalf), 0.5f);
}

__global__ void __launch_bounds__(128)
lstm_kernel(const float* __restrict__ x,
            const float* __restrict__ W_ih,
            const float* __restrict__ W_hh,
            const float* __restrict__ b_ih,
            const float* __restrict__ b_hh,
            const float* __restrict__ W_out,
            const float* __restrict__ b_out,
            float* __restrict__ out)
{
    __shared__ __align__(16) ulonglong2 wi_sm[I_SZ * 32];        // [i][j] {wif},{wgo}
    __shared__ __align__(16) ulonglong2 wgo_sm[16 * 32];         // [k2][j] {wgo[2k],wgo[2k+1]}
    __shared__ __align__(16) u64 xbuf[4][CHUNK * XT_STRIDE];     // per-warp x dup
    __shared__ __align__(16) u64 hbuf[4][32 * HK_STRIDE];        // per-warp h dup (single buf)

    const int tid  = threadIdx.x;
    const int lane = tid & 31;
    const int warp = tid >> 5;

    // ---- wif (gates i,f; pre-scaled 0.5) -> registers ----
    u64 wif[32];
    {
        const float* ri = W_hh + (0 * 32 + lane) * 32;
        const float* rf = W_hh + (1 * 32 + lane) * 32;
#pragma unroll
        for (int kk = 0; kk < 8; ++kk) {
            const float4 ai = *(const float4*)(ri + kk * 4);
            const float4 af = *(const float4*)(rf + kk * 4);
            wif[kk * 4 + 0] = pack2(0.5f * ai.x, 0.5f * af.x);
            wif[kk * 4 + 1] = pack2(0.5f * ai.y, 0.5f * af.y);
            wif[kk * 4 + 2] = pack2(0.5f * ai.z, 0.5f * af.z);
            wif[kk * 4 + 3] = pack2(0.5f * ai.w, 0.5f * af.w);
        }
    }

    // ---- wgo (gates g,o; o pre-scaled 0.5) -> smem, 2-k packed ----
    for (int idx = tid; idx < 16 * 32; idx += 128) {
        int k2 = idx >> 5, j = idx & 31;
        float g0 =        W_hh[(2 * 32 + j) * 32 + 2 * k2 + 0];
        float o0 = 0.5f * W_hh[(3 * 32 + j) * 32 + 2 * k2 + 0];
        float g1 =        W_hh[(2 * 32 + j) * 32 + 2 * k2 + 1];
        float o1 = 0.5f * W_hh[(3 * 32 + j) * 32 + 2 * k2 + 1];
        wgo_sm[idx] = make_ulonglong2(pack2(g0, o0), pack2(g1, o1));
    }

    // ---- W_ih gate pairs -> smem ----
    for (int idx = tid; idx < I_SZ * 32; idx += 128) {
        int i = idx >> 5, j = idx & 31;
        float a = 0.5f * W_ih[(0 * 32 + j) * I_SZ + i];
        float b = 0.5f * W_ih[(1 * 32 + j) * I_SZ + i];
        float c =        W_ih[(2 * 32 + j) * I_SZ + i];
        float d = 0.5f * W_ih[(3 * 32 + j) * I_SZ + i];
        wi_sm[idx] = make_ulonglong2(pack2(a, b), pack2(c, d));
    }

    // ---- zero h buffer ----
    for (int idx = tid; idx < 4 * 32 * HK_STRIDE; idx += 128)
        ((u64*)hbuf)[idx] = 0ull;
    __syncthreads();

    // ---- biases (gate pairs, i/f/o pre-scaled) ----
    const float bi_ = 0.5f * (b_ih[0 * 32 + lane] + b_hh[0 * 32 + lane]);
    const float bf_ = 0.5f * (b_ih[1 * 32 + lane] + b_hh[1 * 32 + lane]);
    const float bg_ =         b_ih[2 * 32 + lane] + b_hh[2 * 32 + lane];
    const float bo_ = 0.5f * (b_ih[3 * 32 + lane] + b_hh[3 * 32 + lane]);
    const u64 bif = pack2(bi_, bf_);
    const u64 bgo = pack2(bg_, bo_);

    float cs[8], hs[8];
#pragma unroll
    for (int b = 0; b < 8; ++b) { cs[b] = 0.f; hs[b] = 0.f; }

    u64* const xW = xbuf[warp];
    u64* const hW = hbuf[warp];

    const float* xw = x + (size_t)(blockIdx.x * 32 + warp * 8) * T_TOT * I_SZ;
    const int t_ = lane >> 2;           // 0..7
    const int i0 = (lane & 3) * 2;      // 0,2,4,6

    // pipelined x-projection accumulators
    u64 nif[8], ngo[8];
    auto xproj = [&](int s) {
#pragma unroll
        for (int b = 0; b < 8; ++b) { nif[b] = bif; ngo[b] = bgo; }
#pragma unroll
        for (int i = 0; i < I_SZ; ++i) {
            const ulonglong2 wv = wi_sm[i * 32 + lane];
            const u64* xr = xW + s * XT_STRIDE + i * XI_STRIDE;
#pragma unroll
            for (int p = 0; p < 4; ++p) {
                const ulonglong2 xv = *(const ulonglong2*)(xr + 2 * p);
                nif[2*p+0] = fma2(xv.x, wv.x, nif[2*p+0]);
                ngo[2*p+0] = fma2(xv.x, wv.y, ngo[2*p+0]);
                nif[2*p+1] = fma2(xv.y, wv.x, nif[2*p+1]);
                ngo[2*p+1] = fma2(xv.y, wv.y, ngo[2*p+1]);
            }
        }
    };

    // x prefetch registers (chunk ahead): 8 batches x float2
    float2 xpre[8];
#pragma unroll
    for (int b = 0; b < 8; ++b)
        xpre[b] = *(const float2*)(xw + ((size_t)b * T_TOT + 0 * CHUNK + t_) * I_SZ + i0);

#pragma unroll 1
    for (int tc = 0; tc < NCHUNK; ++tc) {
        __syncwarp();
        // ---- stage x chunk from prefetched registers, pre-duplicated {x,x} ----
#pragma unroll
        for (int b = 0; b < 8; ++b) {
            xW[t_ * XT_STRIDE + (i0 + 0) * XI_STRIDE + b] = pack2(xpre[b].x, xpre[b].x);
            xW[t_ * XT_STRIDE + (i0 + 1) * XI_STRIDE + b] = pack2(xpre[b].y, xpre[b].y);
        }
        // ---- prefetch next chunk's x (clamped to stay in-bounds) ----
        {
            const int tcn = (tc + 1 < NCHUNK) ? tc + 1 : tc;
#pragma unroll
            for (int b = 0; b < 8; ++b)
                xpre[b] = *(const float2*)(xw + ((size_t)b * T_TOT + tcn * CHUNK + t_) * I_SZ + i0);
        }
        __syncwarp();

        xproj(0);   // prime pipeline for s=0

#pragma unroll 1
        for (int s = 0; s < CHUNK; ++s) {
            // z starts from pipelined x projection
            u64 zif[8], zgo[8];
#pragma unroll
            for (int b = 0; b < 8; ++b) { zif[b] = nif[b]; zgo[b] = ngo[b]; }

            // ---- recurrent projection: wif regs, wgo smem (2k packed), h broadcast ----
#pragma unroll
            for (int k2 = 0; k2 < 16; ++k2) {
                const ulonglong2 wgo2 = wgo_sm[k2 * 32 + lane];
                const int k0 = 2 * k2, k1 = 2 * k2 + 1;
                const u64* h0p = hW + k0 * HK_STRIDE;
                const u64* h1p = hW + k1 * HK_STRIDE;
#pragma unroll
                for (int p = 0; p < 4; ++p) {
                    const ulonglong2 hv0 = *(const ulonglong2*)(h0p + 2 * p);
                    zif[2*p+0] = fma2(hv0.x, wif[k0], zif[2*p+0]);
                    zgo[2*p+0] = fma2(hv0.x, wgo2.x, zgo[2*p+0]);
                    zif[2*p+1] = fma2(hv0.y, wif[k0], zif[2*p+1]);
                    zgo[2*p+1] = fma2(hv0.y, wgo2.x, zgo[2*p+1]);
                }
#pragma unroll
                for (int p = 0; p < 4; ++p) {
                    const ulonglong2 hv1 = *(const ulonglong2*)(h1p + 2 * p);
                    zif[2*p+0] = fma2(hv1.x, wif[k1], zif[2*p+0]);
                    zgo[2*p+0] = fma2(hv1.x, wgo2.y, zgo[2*p+0]);
                    zif[2*p+1] = fma2(hv1.y, wif[k1], zif[2*p+1]);
                    zgo[2*p+1] = fma2(hv1.y, wgo2.y, zgo[2*p+1]);
                }
            }

            // ---- next step's x projection: independent work overlapping the
            //      activation dependency chain (branch-free; s==7 result is
            //      discarded and recomputed after next staging) ----
            xproj((s + 1) & (CHUNK - 1));

            // ---- gates + state update (8 independent chains) ----
#pragma unroll
            for (int b = 0; b < 8; ++b) {
                float zi, zf, zg, zo;
                unpack2(zif[b], zi, zf); unpack2(zgo[b], zg, zo);
                cs[b] = fmaf(sig_h(zf), cs[b], sig_h(zi) * tanhap(zg));
                hs[b] = sig_h(zo) * tanhap(cs[b]);
            }

            __syncwarp();   // all broadcast reads of hW complete
            {
                u64* hd = hW + lane * HK_STRIDE;
                *(float4*)(hd + 0) = make_float4(hs[0], hs[0], hs[1], hs[1]);
                *(float4*)(hd + 2) = make_float4(hs[2], hs[2], hs[3], hs[3]);
                *(float4*)(hd + 4) = make_float4(hs[4], hs[4], hs[5], hs[5]);
                *(float4*)(hd + 6) = make_float4(hs[6], hs[6], hs[7], hs[7]);
            }
            __syncwarp();   // writes visible before next step's reads
        }
    }

    // ---- output head: out[b] = sum_j h[b][j]*W_out[j] + b_out ----
    const float wo = W_out[lane];
    float v[8];
#pragma unroll
    for (int b = 0; b < 8; ++b) v[b] = hs[b] * wo;
#pragma unroll
    for (int off = 16; off; off >>= 1) {
#pragma unroll
        for (int b = 0; b < 8; ++b)
            v[b] += __shfl_xor_sync(0xffffffffu, v[b], off);
    }
    if (lane == 0) {
        const float bout = b_out[0];
        const int bb = blockIdx.x * 32 + warp * 8;
#pragma unroll
        for (int b = 0; b < 8; ++b) out[bb + b] = v[b] + bout;
    }
}

extern "C" void kernel_launch(void* const* d_in, const int* in_sizes, int n_in,
                              void* d_out, int out_size)
{
    const float* x     = (const float*)d_in[0];
    const float* W_ih  = (const float*)d_in[1];
    const float* W_hh  = (const float*)d_in[2];
    const float* b_ih  = (const float*)d_in[3];
    const float* b_hh  = (const float*)d_in[4];
    const float* W_out = (const float*)d_in[5];
    const float* b_out = (const float*)d_in[6];
    float* out = (float*)d_out;

    lstm_kernel<<<B_TOT / 32, 128>>>(x, W_ih, W_hh, b_ih, b_hh, W_out, b_out, out);
}

// round 10
// speedup vs baseline: 1.4790x; 1.4790x over previous
#include <cuda_runtime.h>
#include <cstdint>

// LSTM B=4096 T=256 I=8 H=32 O=1.
// R2-structure inner loop (empirical best), repackaged as 1-warp CTAs:
//  - CTA = 32 threads = 1 warp = 4 batch sequences; grid = 1024.
//    All CTAs resident (<=7/SM) -> max 28 batch-seqs/SM vs 32 before.
//  - lane j = hidden unit j. f32x2 = natural BATCH pairs {b0,b1},{b2,b3}.
//  - W_hh all 4 gates in registers as duplicated {w,w} pairs (some spill to
//    local/L1 is expected and empirically fine).
//  - h stored as natural pairs (float4 {h0,h1,h2,h3}): recurrent k-iter =
//    1 broadcast LDS.128 + 8 FFMA2, zero packs.
//  - W_ih duplicated pairs in smem; x staged per 16-step chunk.
//  - tanh.approx activations; sigmoid 0.5 scale folded into i,f,o weights.

#define B_TOT 4096
#define T_TOT 256
#define I_SZ 8
#define CHUNK 16
#define XT_STRIDE 36     // floats per t-row (8 i * 4 b + 4 pad), 16B-aligned

typedef unsigned long long u64;

__device__ __forceinline__ u64 pack2(float a, float b) {
    u64 r; asm("mov.b64 %0,{%1,%2};" : "=l"(r) : "f"(a), "f"(b)); return r;
}
__device__ __forceinline__ void unpack2(u64 v, float& a, float& b) {
    asm("mov.b64 {%0,%1},%2;" : "=f"(a), "=f"(b) : "l"(v));
}
__device__ __forceinline__ u64 fma2(u64 a, u64 b, u64 c) {
    u64 d; asm("fma.rn.f32x2 %0,%1,%2,%3;" : "=l"(d) : "l"(a), "l"(b), "l"(c)); return d;
}
__device__ __forceinline__ float tanhap(float x) {
    float y; asm("tanh.approx.f32 %0,%1;" : "=f"(y) : "f"(x)); return y;
}
// i,f,o accumulators pre-scaled by 0.5: sigmoid(z)=0.5*tanh(z/2)+0.5
__device__ __forceinline__ float sig_h(float zhalf) {
    return fmaf(0.5f, tanhap(zhalf), 0.5f);
}

__global__ void __launch_bounds__(32)
lstm_kernel(const float* __restrict__ x,
            const float* __restrict__ W_ih,
            const float* __restrict__ W_hh,
            const float* __restrict__ b_ih,
            const float* __restrict__ b_hh,
            const float* __restrict__ W_out,
            const float* __restrict__ b_out,
            float* __restrict__ out)
{
    // per-CTA (= per-warp) shared buffers
    __shared__ __align__(16) ulonglong2 wiA[I_SZ * 32];  // [i][j] {wi,wi},{wf,wf} (x0.5)
    __shared__ __align__(16) ulonglong2 wiB[I_SZ * 32];  // [i][j] {wg,wg},{wo,wo} (o x0.5)
    __shared__ __align__(16) float x_sm[CHUNK * XT_STRIDE];  // [t][i][b]
    __shared__ __align__(16) float h_sm[2 * 32 * 4];          // [cur][k][b]

    const int lane = threadIdx.x & 31;

    // ---- W_hh rows -> registers, duplicated {w,w} (i,f,o pre-scaled 0.5) ----
    u64 wdi[32], wdf[32], wdg[32], wdo[32];
    {
        const float* ri = W_hh + (0 * 32 + lane) * 32;
        const float* rf = W_hh + (1 * 32 + lane) * 32;
        const float* rg = W_hh + (2 * 32 + lane) * 32;
        const float* ro = W_hh + (3 * 32 + lane) * 32;
#pragma unroll
        for (int kk = 0; kk < 8; ++kk) {
            const float4 ai = *(const float4*)(ri + kk * 4);
            const float4 af = *(const float4*)(rf + kk * 4);
            const float4 ag = *(const float4*)(rg + kk * 4);
            const float4 ao = *(const float4*)(ro + kk * 4);
            wdi[kk*4+0] = pack2(0.5f*ai.x, 0.5f*ai.x);
            wdi[kk*4+1] = pack2(0.5f*ai.y, 0.5f*ai.y);
            wdi[kk*4+2] = pack2(0.5f*ai.z, 0.5f*ai.z);
            wdi[kk*4+3] = pack2(0.5f*ai.w, 0.5f*ai.w);
            wdf[kk*4+0] = pack2(0.5f*af.x, 0.5f*af.x);
            wdf[kk*4+1] = pack2(0.5f*af.y, 0.5f*af.y);
            wdf[kk*4+2] = pack2(0.5f*af.z, 0.5f*af.z);
            wdf[kk*4+3] = pack2(0.5f*af.w, 0.5f*af.w);
            wdg[kk*4+0] = pack2(ag.x, ag.x);
            wdg[kk*4+1] = pack2(ag.y, ag.y);
            wdg[kk*4+2] = pack2(ag.z, ag.z);
            wdg[kk*4+3] = pack2(ag.w, ag.w);
            wdo[kk*4+0] = pack2(0.5f*ao.x, 0.5f*ao.x);
            wdo[kk*4+1] = pack2(0.5f*ao.y, 0.5f*ao.y);
            wdo[kk*4+2] = pack2(0.5f*ao.z, 0.5f*ao.z);
            wdo[kk*4+3] = pack2(0.5f*ao.w, 0.5f*ao.w);
        }
    }

    // ---- W_ih duplicated pairs into smem ----
#pragma unroll
    for (int it = 0; it < I_SZ; ++it) {
        const int i = it, j = lane;
        const float a = 0.5f * W_ih[(0 * 32 + j) * I_SZ + i];
        const float b = 0.5f * W_ih[(1 * 32 + j) * I_SZ + i];
        const float c =        W_ih[(2 * 32 + j) * I_SZ + i];
        const float d = 0.5f * W_ih[(3 * 32 + j) * I_SZ + i];
        wiA[i * 32 + j] = make_ulonglong2(pack2(a, a), pack2(b, b));
        wiB[i * 32 + j] = make_ulonglong2(pack2(c, c), pack2(d, d));
    }

    // ---- zero h buffers ----
    *(float4*)(h_sm + lane * 4)       = make_float4(0.f, 0.f, 0.f, 0.f);
    *(float4*)(h_sm + 128 + lane * 4) = make_float4(0.f, 0.f, 0.f, 0.f);

    // ---- biases (duplicated pairs; i,f,o pre-scaled) ----
    const float bi_ = 0.5f * (b_ih[0 * 32 + lane] + b_hh[0 * 32 + lane]);
    const float bf_ = 0.5f * (b_ih[1 * 32 + lane] + b_hh[1 * 32 + lane]);
    const float bg_ =         b_ih[2 * 32 + lane] + b_hh[2 * 32 + lane];
    const float bo_ = 0.5f * (b_ih[3 * 32 + lane] + b_hh[3 * 32 + lane]);
    const u64 bdi = pack2(bi_, bi_);
    const u64 bdf = pack2(bf_, bf_);
    const u64 bdg = pack2(bg_, bg_);
    const u64 bdo = pack2(bo_, bo_);

    float c0 = 0.f, c1 = 0.f, c2 = 0.f, c3 = 0.f;
    float h0 = 0.f, h1 = 0.f, h2 = 0.f, h3 = 0.f;
    int cur = 0;

    const float* xw = x + (size_t)blockIdx.x * 4 * T_TOT * I_SZ;
    const int t_ = lane >> 1;           // 0..15
    const int i0 = (lane & 1) * 4;      // 0 or 4

    __syncwarp();

#pragma unroll 1
    for (int tc = 0; tc < T_TOT / CHUNK; ++tc) {
        // ---- stage x chunk: x_sm[t][i][b]; lane covers (t_, i0..i0+3) ----
#pragma unroll
        for (int b = 0; b < 4; ++b) {
            const float4 v = *(const float4*)(xw
                + ((size_t)b * T_TOT + tc * CHUNK + t_) * I_SZ + i0);
            float* dst = x_sm + t_ * XT_STRIDE + i0 * 4 + b;
            dst[0]  = v.x;
            dst[4]  = v.y;
            dst[8]  = v.z;
            dst[12] = v.w;
        }
        __syncwarp();

#pragma unroll 1
        for (int s = 0; s < CHUNK; ++s) {
            const float* hr = h_sm + cur * 128;
            float*       hw = h_sm + (cur ^ 1) * 128;

            u64 zi01 = bdi, zi23 = bdi;
            u64 zf01 = bdf, zf23 = bdf;
            u64 zg01 = bdg, zg23 = bdg;
            u64 zo01 = bdo, zo23 = bdo;

            // ---- input projection: broadcast x pairs, per-lane dup weights ----
#pragma unroll
            for (int i = 0; i < I_SZ; ++i) {
                const ulonglong2 xv = *(const ulonglong2*)(x_sm + s * XT_STRIDE + i * 4);
                const ulonglong2 wA = wiA[i * 32 + lane];
                const ulonglong2 wB = wiB[i * 32 + lane];
                zi01 = fma2(xv.x, wA.x, zi01); zi23 = fma2(xv.y, wA.x, zi23);
                zf01 = fma2(xv.x, wA.y, zf01); zf23 = fma2(xv.y, wA.y, zf23);
                zg01 = fma2(xv.x, wB.x, zg01); zg23 = fma2(xv.y, wB.x, zg23);
                zo01 = fma2(xv.x, wB.y, zo01); zo23 = fma2(xv.y, wB.y, zo23);
            }

            // ---- recurrent: 1 broadcast LDS.128 + 8 fma2 per k, reg weights ----
#pragma unroll
            for (int k = 0; k < 32; ++k) {
                const ulonglong2 hv = *(const ulonglong2*)(hr + k * 4);
                zi01 = fma2(hv.x, wdi[k], zi01); zi23 = fma2(hv.y, wdi[k], zi23);
                zf01 = fma2(hv.x, wdf[k], zf01); zf23 = fma2(hv.y, wdf[k], zf23);
                zg01 = fma2(hv.x, wdg[k], zg01); zg23 = fma2(hv.y, wdg[k], zg23);
                zo01 = fma2(hv.x, wdo[k], zo01); zo23 = fma2(hv.y, wdo[k], zo23);
            }

            // ---- gates + state update ----
            float zia, zib, zfa, zfb, zga, zgb, zoa, zob;

            unpack2(zi01, zia, zib); unpack2(zf01, zfa, zfb);
            unpack2(zg01, zga, zgb); unpack2(zo01, zoa, zob);
            c0 = fmaf(sig_h(zfa), c0, sig_h(zia) * tanhap(zga));
            h0 = sig_h(zoa) * tanhap(c0);
            c1 = fmaf(sig_h(zfb), c1, sig_h(zib) * tanhap(zgb));
            h1 = sig_h(zob) * tanhap(c1);

            unpack2(zi23, zia, zib); unpack2(zf23, zfa, zfb);
            unpack2(zg23, zga, zgb); unpack2(zo23, zoa, zob);
            c2 = fmaf(sig_h(zfa), c2, sig_h(zia) * tanhap(zga));
            h2 = sig_h(zoa) * tanhap(c2);
            c3 = fmaf(sig_h(zfb), c3, sig_h(zib) * tanhap(zgb));
            h3 = sig_h(zob) * tanhap(c3);

            // store h pairs for next step (conflict-free STS.128)
            *(float4*)(hw + lane * 4) = make_float4(h0, h1, h2, h3);
            cur ^= 1;
            __syncwarp();
        }
    }

    // ---- output head: out[b] = sum_j h[b][j]*W_out[j] + b_out ----
    const float wo = W_out[lane];
    float v0 = h0 * wo, v1 = h1 * wo, v2 = h2 * wo, v3 = h3 * wo;
#pragma unroll
    for (int off = 16; off; off >>= 1) {
        v0 += __shfl_xor_sync(0xffffffffu, v0, off);
        v1 += __shfl_xor_sync(0xffffffffu, v1, off);
        v2 += __shfl_xor_sync(0xffffffffu, v2, off);
        v3 += __shfl_xor_sync(0xffffffffu, v3, off);
    }
    if (lane == 0) {
        const float bout = b_out[0];
        const int bb = blockIdx.x * 4;
        out[bb + 0] = v0 + bout;
        out[bb + 1] = v1 + bout;
        out[bb + 2] = v2 + bout;
        out[bb + 3] = v3 + bout;
    }
}

extern "C" void kernel_launch(void* const* d_in, const int* in_sizes, int n_in,
                              void* d_out, int out_size)
{
    const float* x     = (const float*)d_in[0];
    const float* W_ih  = (const float*)d_in[1];
    const float* W_hh  = (const float*)d_in[2];
    const float* b_ih  = (const float*)d_in[3];
    const float* b_hh  = (const float*)d_in[4];
    const float* W_out = (const float*)d_in[5];
    const float* b_out = (const float*)d_in[6];
    float* out = (float*)d_out;

    lstm_kernel<<<B_TOT / 4, 32>>>(x, W_ih, W_hh, b_ih, b_hh, W_out, b_out, out);
}